// round 1
// baseline (speedup 1.0000x reference)
#include <cuda_runtime.h>

typedef unsigned long long ull;

#define NA    8
#define BATCH 32768
#define DD    128
#define HHH   128
#define AADIM 64
#define EE    32
#define BM    128
#define SA    130   // stride (floats) for sA / sC (8B-aligned rows, bank-safe)
#define SWC   130   // stride for constraint weights

// smem float offsets
#define OFF_SA    0
#define OFF_SC    (BM * SA)                    // 16640
#define OFF_SB    (OFF_SC + BM * SA)           // 33280
#define OFF_SWC   (OFF_SB + 128 * 128)         // 49664
#define OFF_SG    (OFF_SWC + 33 * SWC)         // 53954
#define OFF_CSUM  (OFF_SG + 128)               // 54082
#define OFF_RED   (OFF_CSUM + 128)             // 54210
#define SMEM_FLOATS (OFF_RED + 256)            // 54466
#define SMEM_BYTES (SMEM_FLOATS * 4)           // 217864

__device__ __forceinline__ void fma2(ull& c, ull a, ull b) {
#if __CUDA_ARCH__ >= 1000
    asm("fma.rn.f32x2 %0, %1, %2, %0;" : "+l"(c) : "l"(a), "l"(b));
#else
    float cx = __uint_as_float((unsigned)c), cy = __uint_as_float((unsigned)(c >> 32));
    float ax = __uint_as_float((unsigned)a), ay = __uint_as_float((unsigned)(a >> 32));
    float bx = __uint_as_float((unsigned)b), by = __uint_as_float((unsigned)(b >> 32));
    cx = fmaf(ax, bx, cx); cy = fmaf(ay, by, cy);
    c = ((ull)__float_as_uint(cy) << 32) | (ull)__float_as_uint(cx);
#endif
}

__device__ __forceinline__ float hsum2(ull v) {
    return __uint_as_float((unsigned)v) + __uint_as_float((unsigned)(v >> 32));
}

// one MLP layer: dst[m][h] = relu(src[m][:] @ W + bias[h]); W pre-staged in sB
// (transposed+swizzled: sB[h*128 + ((k + 2*(h>>3)) & 127)] = W[k][h])
__device__ __forceinline__ void mlp_layer128(
    const float* __restrict__ src, const float* __restrict__ sB,
    float* __restrict__ dst, const float* __restrict__ bias,
    int m0, int h0, int tx)
{
    ull acc[8][8];
#pragma unroll
    for (int i = 0; i < 8; i++)
#pragma unroll
        for (int j = 0; j < 8; j++) acc[i][j] = 0ull;

    const float* pa = src + m0 * SA;
    const float* pb = sB + h0 * 128;
    const int rot2 = 2 * tx;   // (h0+j)>>3 == tx for all j in [0,8)

#pragma unroll 4
    for (int kp = 0; kp < 64; kp++) {
        ull a2[8];
#pragma unroll
        for (int i = 0; i < 8; i++)
            a2[i] = *(const ull*)(pa + i * SA + 2 * kp);
        const int col = (2 * kp + rot2) & 127;
        ull b2[8];
#pragma unroll
        for (int j = 0; j < 8; j++)
            b2[j] = *(const ull*)(pb + j * 128 + col);
#pragma unroll
        for (int i = 0; i < 8; i++)
#pragma unroll
            for (int j = 0; j < 8; j++)
                fma2(acc[i][j], a2[i], b2[j]);
    }

    float bj[8];
#pragma unroll
    for (int j = 0; j < 8; j++) bj[j] = __ldg(bias + h0 + j);

#pragma unroll
    for (int i = 0; i < 8; i++) {
#pragma unroll
        for (int j2 = 0; j2 < 4; j2++) {
            float x = fmaxf(hsum2(acc[i][2 * j2])     + bj[2 * j2],     0.f);
            float y = fmaxf(hsum2(acc[i][2 * j2 + 1]) + bj[2 * j2 + 1], 0.f);
            *(float2*)(dst + (m0 + i) * SA + h0 + 2 * j2) = make_float2(x, y);
        }
    }
}

extern "C" __global__ void __launch_bounds__(256, 1)
qatten_kernel(const float* __restrict__ states,
              const float* __restrict__ W1, const float* __restrict__ b1,
              const float* __restrict__ W2, const float* __restrict__ b2,
              const float* __restrict__ W3, const float* __restrict__ b3,
              const float* __restrict__ Ws1, const float* __restrict__ bs1,
              const float* __restrict__ Ws2, const float* __restrict__ bs2,
              const float* __restrict__ Wc1, const float* __restrict__ bc1,
              const float* __restrict__ Wc2, const float* __restrict__ bc2,
              float* __restrict__ out)
{
    extern __shared__ float sm[];
    float* sA    = sm + OFF_SA;
    float* sC    = sm + OFF_SC;
    float* sB    = sm + OFF_SB;
    float* sWc   = sm + OFF_SWC;
    float* sG    = sm + OFF_SG;
    float* sCsum = sm + OFF_CSUM;
    float* sRed  = sm + OFF_RED;

    const int tid = threadIdx.x;
    const int tx = tid & 15, ty = tid >> 4;
    const int m0 = ty * 8, h0 = tx * 8, a0 = tx * 4;
    const int b0 = blockIdx.x * BM;

    // stage shared constraint/scaling weights once: sWc[e][k]=Wc1[k][e], sWc[32][k]=Ws1[k]
    for (int idx = tid * 4; idx < DD * EE; idx += 256 * 4) {
        float4 w = *(const float4*)(Wc1 + idx);
        int k = idx >> 5, e = idx & 31;
        sWc[(e + 0) * SWC + k] = w.x;
        sWc[(e + 1) * SWC + k] = w.y;
        sWc[(e + 2) * SWC + k] = w.z;
        sWc[(e + 3) * SWC + k] = w.w;
    }
    if (tid < 128) sWc[32 * SWC + tid] = __ldg(Ws1 + tid);

    float oacc[8][4];
#pragma unroll
    for (int i = 0; i < 8; i++)
#pragma unroll
        for (int j = 0; j < 4; j++) oacc[i][j] = 0.f;

    for (int n = 0; n < NA; n++) {
        __syncthreads();  // previous agent done with sA/sB (and sWc staged on n==0)

        // ---- load S tile -> sA[m][k] ----
        const float* Sp = states + ((size_t)n * BATCH + b0) * DD;
#pragma unroll
        for (int i = 0; i < 16; i++) {
            int idx = i * 1024 + tid * 4;
            int m = idx >> 7, k = idx & 127;
            float4 v = *(const float4*)(Sp + idx);
            float* p = sA + m * SA + k;
            *(float2*)(p)     = make_float2(v.x, v.y);
            *(float2*)(p + 2) = make_float2(v.z, v.w);
        }
        // ---- load W1 transposed+swizzled -> sB ----
        const float* W1p = W1 + n * DD * HHH;
#pragma unroll
        for (int i = 0; i < 16; i++) {
            int idx = i * 1024 + tid * 4;
            int k = idx >> 7, h = idx & 127;
            float4 w = *(const float4*)(W1p + idx);
            sB[(h + 0) * 128 + ((k + 2 * ((h + 0) >> 3)) & 127)] = w.x;
            sB[(h + 1) * 128 + ((k + 2 * ((h + 1) >> 3)) & 127)] = w.y;
            sB[(h + 2) * 128 + ((k + 2 * ((h + 2) >> 3)) & 127)] = w.z;
            sB[(h + 3) * 128 + ((k + 2 * ((h + 3) >> 3)) & 127)] = w.w;
        }
        __syncthreads();

        // ---- shared constraint + scaling MLPs (read sA, sWc) ----
        {
            const int row = tid >> 1;
            const int half = tid & 1;
            ull ac[16];
#pragma unroll
            for (int e = 0; e < 16; e++) ac[e] = 0ull;
            ull as_ = 0ull;
            const float* pa = sA + row * SA;
            const float* pw = sWc + (half * 16) * SWC;
            const float* ps = sWc + 32 * SWC;
#pragma unroll 2
            for (int kp = 0; kp < 64; kp++) {
                ull a2 = *(const ull*)(pa + 2 * kp);
#pragma unroll
                for (int e = 0; e < 16; e++) {
                    ull w2 = *(const ull*)(pw + e * SWC + 2 * kp);
                    fma2(ac[e], a2, w2);
                }
                if (half == 0) {
                    ull w2 = *(const ull*)(ps + 2 * kp);
                    fma2(as_, a2, w2);
                }
            }
            float cpart = 0.f;
#pragma unroll
            for (int e = 0; e < 16; e++) {
                float c1 = fmaxf(hsum2(ac[e]) + __ldg(bc1 + half * 16 + e), 0.f);
                cpart = fmaf(c1, __ldg(Wc2 + half * 16 + e), cpart);
            }
            sRed[row * 2 + half] = cpart;
            if (half == 0) {
                float s1 = fmaxf(hsum2(as_) + __ldg(bs1), 0.f);
                float s2 = fmaf(s1, __ldg(Ws2), __ldg(bs2));
                sG[row] = 1.f / (1.f + __expf(-s2));
            }
            __syncthreads();
            if (half == 0) {
                float c2 = sRed[row * 2] + sRed[row * 2 + 1] + __ldg(bc2);
                if (n == 0) sCsum[row] = c2; else sCsum[row] += c2;
            }
        }

        // ---- layer 1: sC = relu(sA @ W1 + b1) ----
        mlp_layer128(sA, sB, sC, b1 + n * HHH, m0, h0, tx);
        __syncthreads();

        // ---- load W2 -> sB ----
        const float* W2p = W2 + n * HHH * HHH;
#pragma unroll
        for (int i = 0; i < 16; i++) {
            int idx = i * 1024 + tid * 4;
            int k = idx >> 7, h = idx & 127;
            float4 w = *(const float4*)(W2p + idx);
            sB[(h + 0) * 128 + ((k + 2 * ((h + 0) >> 3)) & 127)] = w.x;
            sB[(h + 1) * 128 + ((k + 2 * ((h + 1) >> 3)) & 127)] = w.y;
            sB[(h + 2) * 128 + ((k + 2 * ((h + 2) >> 3)) & 127)] = w.z;
            sB[(h + 3) * 128 + ((k + 2 * ((h + 3) >> 3)) & 127)] = w.w;
        }
        __syncthreads();

        // ---- layer 2: sA = relu(sC @ W2 + b2) ----
        mlp_layer128(sC, sB, sA, b2 + n * HHH, m0, h0, tx);
        __syncthreads();

        // ---- load W3 (128x64) -> sB ----
        const float* W3p = W3 + n * HHH * AADIM;
#pragma unroll
        for (int i = 0; i < 8; i++) {
            int idx = i * 1024 + tid * 4;
            int k = idx >> 6, a = idx & 63;
            float4 w = *(const float4*)(W3p + idx);
            sB[(a + 0) * 128 + ((k + 2 * ((a + 0) >> 3)) & 127)] = w.x;
            sB[(a + 1) * 128 + ((k + 2 * ((a + 1) >> 3)) & 127)] = w.y;
            sB[(a + 2) * 128 + ((k + 2 * ((a + 2) >> 3)) & 127)] = w.z;
            sB[(a + 3) * 128 + ((k + 2 * ((a + 3) >> 3)) & 127)] = w.w;
        }
        __syncthreads();

        // ---- layer 3 + gated accumulation: oacc += g[m] * (sA @ W3 + b3) ----
        {
            ull acc[8][4];
#pragma unroll
            for (int i = 0; i < 8; i++)
#pragma unroll
                for (int j = 0; j < 4; j++) acc[i][j] = 0ull;
            const float* pa = sA + m0 * SA;
            int colr[4];
#pragma unroll
            for (int j = 0; j < 4; j++) colr[j] = 2 * ((a0 + j) >> 3);
#pragma unroll 4
            for (int kp = 0; kp < 64; kp++) {
                ull a2[8];
#pragma unroll
                for (int i = 0; i < 8; i++)
                    a2[i] = *(const ull*)(pa + i * SA + 2 * kp);
                ull b2[4];
#pragma unroll
                for (int j = 0; j < 4; j++)
                    b2[j] = *(const ull*)(sB + (a0 + j) * 128 + ((2 * kp + colr[j]) & 127));
#pragma unroll
                for (int i = 0; i < 8; i++)
#pragma unroll
                    for (int j = 0; j < 4; j++)
                        fma2(acc[i][j], a2[i], b2[j]);
            }
            const float* b3n = b3 + n * AADIM;
            float bj[4];
#pragma unroll
            for (int j = 0; j < 4; j++) bj[j] = __ldg(b3n + a0 + j);
#pragma unroll
            for (int i = 0; i < 8; i++) {
                float g = sG[m0 + i];
#pragma unroll
                for (int j = 0; j < 4; j++) {
                    float q = hsum2(acc[i][j]) + bj[j];
                    oacc[i][j] = fmaf(g, q, oacc[i][j]);
                }
            }
        }
    }

    __syncthreads();
    // ---- epilogue: out[b][a] = oacc/8 + csum/8 ----
#pragma unroll
    for (int i = 0; i < 8; i++) {
        int m = m0 + i;
        float cs = sCsum[m] * 0.125f;
        float4 v;
        v.x = fmaf(oacc[i][0], 0.125f, cs);
        v.y = fmaf(oacc[i][1], 0.125f, cs);
        v.z = fmaf(oacc[i][2], 0.125f, cs);
        v.w = fmaf(oacc[i][3], 0.125f, cs);
        *(float4*)(out + (size_t)(b0 + m) * AADIM + a0) = v;
    }
}

extern "C" void kernel_launch(void* const* d_in, const int* in_sizes, int n_in,
                              void* d_out, int out_size)
{
    const float* states = (const float*)d_in[0];
    const float* W1  = (const float*)d_in[1];
    const float* b1  = (const float*)d_in[2];
    const float* W2  = (const float*)d_in[3];
    const float* b2  = (const float*)d_in[4];
    const float* W3  = (const float*)d_in[5];
    const float* b3  = (const float*)d_in[6];
    // d_in[7..12]: Wq1,bq1,Wq2,bq2,Wk,bk — dead code (softmax rows sum to 1)
    const float* Ws1 = (const float*)d_in[13];
    const float* bs1 = (const float*)d_in[14];
    const float* Ws2 = (const float*)d_in[15];
    const float* bs2 = (const float*)d_in[16];
    const float* Wc1 = (const float*)d_in[17];
    const float* bc1 = (const float*)d_in[18];
    const float* Wc2 = (const float*)d_in[19];
    const float* bc2 = (const float*)d_in[20];
    float* out = (float*)d_out;

    cudaFuncSetAttribute(qatten_kernel,
                         cudaFuncAttributeMaxDynamicSharedMemorySize, SMEM_BYTES);

    qatten_kernel<<<BATCH / BM, 256, SMEM_BYTES>>>(
        states, W1, b1, W2, b2, W3, b3,
        Ws1, bs1, Ws2, bs2, Wc1, bc1, Wc2, bc2, out);
}